// round 11
// baseline (speedup 1.0000x reference)
#include <cuda_runtime.h>
#include <cstdint>
#include <cstddef>

#define BB 4
#define NN 512
#define FF 16
#define EE 64
#define THREADS 128

#define LR_A 0.505f
#define LR_B 0.495f

typedef unsigned long long u64;
typedef unsigned int u32;

__device__ __forceinline__ u64 pk2(float lo, float hi) {
    u64 d; asm("mov.b64 %0, {%1, %2};" : "=l"(d) : "f"(lo), "f"(hi)); return d;
}
__device__ __forceinline__ void upk2(u64 v, float& lo, float& hi) {
    asm("mov.b64 {%0, %1}, %2;" : "=f"(lo), "=f"(hi) : "l"(v));
}
__device__ __forceinline__ u64 pku2(u32 lo, u32 hi) {
    u64 d; asm("mov.b64 %0, {%1, %2};" : "=l"(d) : "r"(lo), "r"(hi)); return d;
}
__device__ __forceinline__ void upku2(u64 v, u32& lo, u32& hi) {
    asm("mov.b64 {%0, %1}, %2;" : "=r"(lo), "=r"(hi) : "l"(v));
}
__device__ __forceinline__ u64 ffma2(u64 a, u64 b, u64 c) {
    u64 d; asm("fma.rn.f32x2 %0, %1, %2, %3;" : "=l"(d) : "l"(a), "l"(b), "l"(c)); return d;
}
__device__ __forceinline__ unsigned smem_u32(const void* p) {
    unsigned r;
    asm("{ .reg .u64 t; cvta.to.shared.u64 t, %1; cvt.u32.u64 %0, t; }" : "=r"(r) : "l"(p));
    return r;
}
__device__ __forceinline__ void cp16(unsigned d, const void* s) {
    asm volatile("cp.async.cg.shared.global [%0], [%1], 16;" :: "r"(d), "l"(s));
}
__device__ __forceinline__ void cpcommit() { asm volatile("cp.async.commit_group;" ::: "memory"); }
template <int N> __device__ __forceinline__ void cpwait() {
    asm volatile("cp.async.wait_group %0;" :: "n"(N) : "memory");
}

// pack two f32 -> bf16x2 (first arg -> low half)
__device__ __forceinline__ u32 pk_bf16(float lo, float hi) {
    u32 d; asm("cvt.rn.bf16x2.f32 %0, %1, %2;" : "=r"(d) : "f"(hi), "f"(lo)); return d;
}
__device__ __forceinline__ float bf_lo(u32 p) { return __uint_as_float(p << 16); }
__device__ __forceinline__ float bf_hi(u32 p) { return __uint_as_float(p & 0xFFFF0000u); }

__device__ __forceinline__ void split2(float x0, float x1, u32& hi, u32& lo) {
    hi = pk_bf16(x0, x1);
    lo = pk_bf16(x0 - bf_lo(hi), x1 - bf_hi(hi));
}

// D(m16n8) += A(m16k16,bf16) * B(k16n8,bf16)
__device__ __forceinline__ void mma16(float d[4], const u32 a[4], const u32 b[2]) {
    asm volatile("mma.sync.aligned.m16n8k16.row.col.f32.bf16.bf16.f32 "
        "{%0,%1,%2,%3}, {%4,%5,%6,%7}, {%8,%9}, {%0,%1,%2,%3};"
        : "+f"(d[0]), "+f"(d[1]), "+f"(d[2]), "+f"(d[3])
        : "r"(a[0]), "r"(a[1]), "r"(a[2]), "r"(a[3]), "r"(b[0]), "r"(b[1]));
}

__global__ void __launch_bounds__(THREADS, 6)
edge_embed_bf16_kernel(const float* __restrict__ edge,
                       const float* __restrict__ adj,
                       const float* __restrict__ w4,
                       const float* __restrict__ w3,
                       float* __restrict__ out)
{
    __shared__ float adj_s[NN];
    __shared__ u64 WloS[8][32];      // warp-invariant Wlo table, 2 KB
    __shared__ float Sp[4][EE];
    __shared__ float Sh[EE];

    const int tid  = threadIdx.x;
    const int lane = tid & 31;
    const int warp = tid >> 5;
    const int gid  = lane >> 2;      // 0..7
    const int tig  = lane & 3;       // 0..3
    const int row  = blockIdx.x;     // b*N + i

    const float* erow = edge + (size_t)row * (NN * FF);
    const float* arow = adj  + (size_t)row * NN;

    cp16(smem_u32(&adj_s[tid * 4]), arow + tid * 4);
    cpcommit();

    // ---- W4 fragments (k-permuted). Whi in regs; Wlo in shared (same for all warps)
    u32 Whi[8][2];
#pragma unroll
    for (int nt = 0; nt < 8; ++nt) {
        const int n = nt * 8 + gid;
        float4 w = __ldg(reinterpret_cast<const float4*>(w4 + n * FF) + tig);
        u32 l0, l1;
        split2(w.x, w.y, Whi[nt][0], l0);
        split2(w.z, w.w, Whi[nt][1], l1);
        if (warp == 0) WloS[nt][lane] = pku2(l0, l1);
    }

    u64 acc2[8];
#pragma unroll
    for (int i = 0; i < 8; ++i) acc2[i] = 0ULL;
    const u64 ABS2 = 0x7FFFFFFF7FFFFFFFULL;

    cpwait<0>();
    __syncthreads();

    // A-frag source (k-permuted): one float4 per row (chunk tig of row j)
    const float4* ev = reinterpret_cast<const float4*>(erow);

    const int jbase = warp * 128;
    float4 x0 = __ldg(ev + (size_t)(jbase + gid) * 4 + tig);
    float4 x1 = __ldg(ev + (size_t)(jbase + gid + 8) * 4 + tig);

    // ---- main loop: 8 m-tiles (16 j each) per warp ----
#pragma unroll
    for (int i = 0; i < 8; ++i) {
        const int j0 = jbase + i * 16;

        float4 c0 = x0, c1 = x1;
        if (i + 1 < 8) {
            const int jn = jbase + (i + 1) * 16;
            x0 = __ldg(ev + (size_t)(jn + gid) * 4 + tig);
            x1 = __ldg(ev + (size_t)(jn + gid + 8) * 4 + tig);
        }

        u32 Ahi[4], Alo[4];
        split2(c0.x, c0.y, Ahi[0], Alo[0]);
        split2(c1.x, c1.y, Ahi[1], Alo[1]);
        split2(c0.z, c0.w, Ahi[2], Alo[2]);
        split2(c1.z, c1.w, Ahi[3], Alo[3]);

        const float aj0 = adj_s[j0 + gid];
        const float aj1 = adj_s[j0 + gid + 8];
        const u64 A0 = pk2(aj0 * LR_A, aj0 * LR_A);
        const u64 B0 = pk2(aj0 * LR_B, aj0 * LR_B);
        const u64 A1 = pk2(aj1 * LR_A, aj1 * LR_A);
        const u64 B1 = pk2(aj1 * LR_B, aj1 * LR_B);

#pragma unroll
        for (int nt = 0; nt < 8; ++nt) {
            u32 wlo[2];
            upku2(WloS[nt][lane], wlo[0], wlo[1]);   // LDS.64, conflict-free

            float d[4] = {0.f, 0.f, 0.f, 0.f};
            float e[4] = {0.f, 0.f, 0.f, 0.f};
            mma16(d, Ahi, Whi[nt]);      // chain d: 1 MMA
            mma16(e, Alo, Whi[nt]);      // chain e: 2 MMAs
            mma16(e, Ahi, wlo);

            const float v0 = d[0] + e[0];
            const float v1 = d[1] + e[1];
            const float v2 = d[2] + e[2];
            const float v3 = d[3] + e[3];
            u64 v01 = pk2(v0, v1);
            u64 v23 = pk2(v2, v3);
            acc2[nt] = ffma2(A0, v01,        acc2[nt]);
            acc2[nt] = ffma2(B0, v01 & ABS2, acc2[nt]);
            acc2[nt] = ffma2(A1, v23,        acc2[nt]);
            acc2[nt] = ffma2(B1, v23 & ABS2, acc2[nt]);
        }
    }

    // ---- reduce over gid (lanes differing by 4,8,16) ----
    float accf[16];
#pragma unroll
    for (int nt = 0; nt < 8; ++nt) upk2(acc2[nt], accf[2 * nt], accf[2 * nt + 1]);
#pragma unroll
    for (int off = 16; off >= 4; off >>= 1) {
#pragma unroll
        for (int i = 0; i < 16; ++i)
            accf[i] += __shfl_down_sync(0xFFFFFFFFu, accf[i], off);
    }
    if (lane < 4) {
#pragma unroll
        for (int nt = 0; nt < 8; ++nt) {
            Sp[warp][nt * 8 + 2 * lane]     = accf[2 * nt];
            Sp[warp][nt * 8 + 2 * lane + 1] = accf[2 * nt + 1];
        }
    }
    __syncthreads();

    if (tid < EE) {
        Sh[tid] = Sp[0][tid] + Sp[1][tid] + Sp[2][tid] + Sp[3][tid];
    }
    __syncthreads();

    // ---- theta3 ----
    if (tid < EE) {
        const float4* w3v = reinterpret_cast<const float4*>(w3 + tid * EE);
        float o = 0.0f;
#pragma unroll
        for (int k = 0; k < 16; ++k) {
            float4 w = __ldg(w3v + k);
            o = fmaf(w.x, Sh[4 * k + 0], o);
            o = fmaf(w.y, Sh[4 * k + 1], o);
            o = fmaf(w.z, Sh[4 * k + 2], o);
            o = fmaf(w.w, Sh[4 * k + 3], o);
        }
        out[(size_t)row * EE + tid] = o;
    }
}

extern "C" void kernel_launch(void* const* d_in, const int* in_sizes, int n_in,
                              void* d_out, int out_size) {
    const float* edge = (const float*)d_in[0];   // (4,512,512,16) f32
    const float* adj  = (const float*)d_in[1];   // (4,512,512)    f32
    const float* w4   = (const float*)d_in[2];   // (64,16)        f32
    const float* w3   = (const float*)d_in[3];   // (64,64)        f32
    float* out = (float*)d_out;                  // (4,512,64)     f32

    edge_embed_bf16_kernel<<<BB * NN, THREADS>>>(edge, adj, w4, w3, out);
}

// round 12
// speedup vs baseline: 1.0554x; 1.0554x over previous
#include <cuda_runtime.h>
#include <cstdint>
#include <cstddef>

#define BB 4
#define NN 512
#define FF 16
#define EE 64
#define THREADS 128

#define LR_A 0.505f
#define LR_B 0.495f

typedef unsigned long long u64;
typedef unsigned int u32;

__device__ __forceinline__ u64 pk2(float lo, float hi) {
    u64 d; asm("mov.b64 %0, {%1, %2};" : "=l"(d) : "f"(lo), "f"(hi)); return d;
}
__device__ __forceinline__ void upk2(u64 v, float& lo, float& hi) {
    asm("mov.b64 {%0, %1}, %2;" : "=f"(lo), "=f"(hi) : "l"(v));
}
__device__ __forceinline__ u64 ffma2(u64 a, u64 b, u64 c) {
    u64 d; asm("fma.rn.f32x2 %0, %1, %2, %3;" : "=l"(d) : "l"(a), "l"(b), "l"(c)); return d;
}
__device__ __forceinline__ u64 fmul2(u64 a, u64 b) {
    u64 d; asm("mul.rn.f32x2 %0, %1, %2;" : "=l"(d) : "l"(a), "l"(b)); return d;
}
__device__ __forceinline__ unsigned smem_u32(const void* p) {
    unsigned r;
    asm("{ .reg .u64 t; cvta.to.shared.u64 t, %1; cvt.u32.u64 %0, t; }" : "=r"(r) : "l"(p));
    return r;
}
__device__ __forceinline__ void cp16(unsigned d, const void* s) {
    asm volatile("cp.async.cg.shared.global [%0], [%1], 16;" :: "r"(d), "l"(s));
}
__device__ __forceinline__ void cpcommit() { asm volatile("cp.async.commit_group;" ::: "memory"); }
template <int N> __device__ __forceinline__ void cpwait() {
    asm volatile("cp.async.wait_group %0;" :: "n"(N) : "memory");
}

// pack two f32 -> bf16x2 (first arg -> low half)
__device__ __forceinline__ u32 pk_bf16(float lo, float hi) {
    u32 d; asm("cvt.rn.bf16x2.f32 %0, %1, %2;" : "=r"(d) : "f"(hi), "f"(lo)); return d;
}
__device__ __forceinline__ float bf_lo(u32 p) { return __uint_as_float(p << 16); }
__device__ __forceinline__ float bf_hi(u32 p) { return __uint_as_float(p & 0xFFFF0000u); }

__device__ __forceinline__ void split2(float x0, float x1, u32& hi, u32& lo) {
    hi = pk_bf16(x0, x1);
    lo = pk_bf16(x0 - bf_lo(hi), x1 - bf_hi(hi));
}

// D(m16n8) += A(m16k16,bf16) * B(k16n8,bf16)
__device__ __forceinline__ void mma16(float d[4], const u32 a[4], const u32 b[2]) {
    asm volatile("mma.sync.aligned.m16n8k16.row.col.f32.bf16.bf16.f32 "
        "{%0,%1,%2,%3}, {%4,%5,%6,%7}, {%8,%9}, {%0,%1,%2,%3};"
        : "+f"(d[0]), "+f"(d[1]), "+f"(d[2]), "+f"(d[3])
        : "r"(a[0]), "r"(a[1]), "r"(a[2]), "r"(a[3]), "r"(b[0]), "r"(b[1]));
}

__global__ void __launch_bounds__(THREADS, 6)
edge_embed_bf16_kernel(const float* __restrict__ edge,
                       const float* __restrict__ adj,
                       const float* __restrict__ w4,
                       const float* __restrict__ w3,
                       float* __restrict__ out)
{
    __shared__ float adj_s[NN];
    __shared__ float Sp[4][EE];
    __shared__ float Sh[EE];

    const int tid  = threadIdx.x;
    const int lane = tid & 31;
    const int warp = tid >> 5;
    const int gid  = lane >> 2;      // 0..7  (MMA row-group / B column)
    const int tig  = lane & 3;       // 0..3  (k chunk / D column pair)
    const int row  = blockIdx.x;     // b*N + i

    const float* erow = edge + (size_t)row * (NN * FF);
    const float* arow = adj  + (size_t)row * NN;

    cp16(smem_u32(&adj_s[tid * 4]), arow + tid * 4);
    cpcommit();

    // ---- A = W4, all 4 e-tiles pre-split in registers (k-permuted chunks) ----
    // a0: e-row et*16+gid,  k 2t..2t+1   <- w4[e0] chunk tig (.x,.y)
    // a1: e-row et*16+gid+8, same k      <- w4[e1] (.x,.y)
    // a2: e-row e0, k 2t+8..2t+9         <- w4[e0] (.z,.w)
    // a3: e-row e1, k 2t+8..2t+9         <- w4[e1] (.z,.w)
    u32 Whi[4][4], Wlo[4][4];
#pragma unroll
    for (int et = 0; et < 4; ++et) {
        const int e0 = et * 16 + gid;
        float4 wa = __ldg(reinterpret_cast<const float4*>(w4 + e0 * FF) + tig);
        float4 wb = __ldg(reinterpret_cast<const float4*>(w4 + (e0 + 8) * FF) + tig);
        split2(wa.x, wa.y, Whi[et][0], Wlo[et][0]);
        split2(wb.x, wb.y, Whi[et][1], Wlo[et][1]);
        split2(wa.z, wa.w, Whi[et][2], Wlo[et][2]);
        split2(wb.z, wb.w, Whi[et][3], Wlo[et][3]);
    }

    // acc2[et*2+r]: packed (j-even, j-odd) partial sums for e = et*16+gid+8r
    u64 acc2[8];
#pragma unroll
    for (int i = 0; i < 8; ++i) acc2[i] = 0ULL;
    const u64 ABS2 = 0x7FFFFFFF7FFFFFFFULL;
    const u64 LRA2 = pk2(LR_A, LR_A);
    const u64 LRB2 = pk2(LR_B, LR_B);

    cpwait<0>();
    __syncthreads();

    // B = edge. Group of 8 j; lane supplies column j = jb+gid, k chunk tig.
    const float4* ev = reinterpret_cast<const float4*>(erow);
    const int jb0 = warp * 128;                    // 16 groups of 8 j per warp

    float4 xa = __ldg(ev + (size_t)(jb0 + gid) * 4 + tig);
    float4 xb = __ldg(ev + (size_t)(jb0 + 8 + gid) * 4 + tig);

#pragma unroll
    for (int gg = 0; gg < 16; ++gg) {
        const int jb = jb0 + gg * 8;
        float4 c = (gg & 1) ? xb : xa;
        if (gg + 2 < 16) {
            float4 nx = __ldg(ev + (size_t)(jb + 16 + gid) * 4 + tig);
            if (gg & 1) xb = nx; else xa = nx;
        }

        // B fragments (hi/lo split)
        u32 bh[2], bl[2];
        split2(c.x, c.y, bh[0], bl[0]);     // k 2t..2t+1
        split2(c.z, c.w, bh[1], bl[1]);     // k 2t+8..2t+9

        // adj pair for this thread's two D columns (j = jb+2t, jb+2t+1)
        float2 aj = *reinterpret_cast<const float2*>(&adj_s[jb + 2 * tig]);
        const u64 a01 = pk2(aj.x, aj.y);
        const u64 aA2 = fmul2(a01, LRA2);
        const u64 aB2 = fmul2(a01, LRB2);

#pragma unroll
        for (int et = 0; et < 4; ++et) {
            float d[4] = {0.f, 0.f, 0.f, 0.f};
            mma16(d, Whi[et], bh);          // hi * hi
            mma16(d, Wlo[et], bh);          // lo * hi
            mma16(d, Whi[et], bl);          // hi * lo
            // d0,d1 -> (e=et*16+gid,  j=jb+2t, jb+2t+1)
            // d2,d3 -> (e=et*16+gid+8, same j)
            u64 v01 = pk2(d[0], d[1]);
            u64 v23 = pk2(d[2], d[3]);
            acc2[et * 2]     = ffma2(aA2, v01,        acc2[et * 2]);
            acc2[et * 2]     = ffma2(aB2, v01 & ABS2, acc2[et * 2]);
            acc2[et * 2 + 1] = ffma2(aA2, v23,        acc2[et * 2 + 1]);
            acc2[et * 2 + 1] = ffma2(aB2, v23 & ABS2, acc2[et * 2 + 1]);
        }
    }

    // ---- reduce: combine j-parity halves, then over tig (quad) ----
    float accf[8];
#pragma unroll
    for (int i = 0; i < 8; ++i) {
        float lo, hi; upk2(acc2[i], lo, hi);
        accf[i] = lo + hi;
    }
#pragma unroll
    for (int off = 1; off <= 2; off <<= 1) {
#pragma unroll
        for (int i = 0; i < 8; ++i)
            accf[i] += __shfl_xor_sync(0xFFFFFFFFu, accf[i], off);
    }
    if (tig == 0) {
#pragma unroll
        for (int et = 0; et < 4; ++et) {
            Sp[warp][et * 16 + gid]     = accf[et * 2];
            Sp[warp][et * 16 + gid + 8] = accf[et * 2 + 1];
        }
    }
    __syncthreads();

    if (tid < EE) {
        Sh[tid] = Sp[0][tid] + Sp[1][tid] + Sp[2][tid] + Sp[3][tid];
    }
    __syncthreads();

    // ---- theta3 ----
    if (tid < EE) {
        const float4* w3v = reinterpret_cast<const float4*>(w3 + tid * EE);
        float o = 0.0f;
#pragma unroll
        for (int k = 0; k < 16; ++k) {
            float4 w = __ldg(w3v + k);
            o = fmaf(w.x, Sh[4 * k + 0], o);
            o = fmaf(w.y, Sh[4 * k + 1], o);
            o = fmaf(w.z, Sh[4 * k + 2], o);
            o = fmaf(w.w, Sh[4 * k + 3], o);
        }
        out[(size_t)row * EE + tid] = o;
    }
}

extern "C" void kernel_launch(void* const* d_in, const int* in_sizes, int n_in,
                              void* d_out, int out_size) {
    const float* edge = (const float*)d_in[0];   // (4,512,512,16) f32
    const float* adj  = (const float*)d_in[1];   // (4,512,512)    f32
    const float* w4   = (const float*)d_in[2];   // (64,16)        f32
    const float* w3   = (const float*)d_in[3];   // (64,64)        f32
    float* out = (float*)d_out;                  // (4,512,64)     f32

    edge_embed_bf16_kernel<<<BB * NN, THREADS>>>(edge, adj, w4, w3, out);
}

// round 14
// speedup vs baseline: 1.0962x; 1.0387x over previous
#include <cuda_runtime.h>
#include <cstdint>
#include <cstddef>

#define BB 4
#define NN 512
#define FF 16
#define EE 64
#define THREADS 128

#define LR_A 0.505f
#define LR_B 0.495f

typedef unsigned long long u64;
typedef unsigned int u32;

__device__ __forceinline__ u64 pk2(float lo, float hi) {
    u64 d; asm("mov.b64 %0, {%1, %2};" : "=l"(d) : "f"(lo), "f"(hi)); return d;
}
__device__ __forceinline__ void upk2(u64 v, float& lo, float& hi) {
    asm("mov.b64 {%0, %1}, %2;" : "=f"(lo), "=f"(hi) : "l"(v));
}
__device__ __forceinline__ u64 ffma2(u64 a, u64 b, u64 c) {
    u64 d; asm("fma.rn.f32x2 %0, %1, %2, %3;" : "=l"(d) : "l"(a), "l"(b), "l"(c)); return d;
}
__device__ __forceinline__ u64 fmul2(u64 a, u64 b) {
    u64 d; asm("mul.rn.f32x2 %0, %1, %2;" : "=l"(d) : "l"(a), "l"(b)); return d;
}
__device__ __forceinline__ unsigned smem_u32(const void* p) {
    unsigned r;
    asm("{ .reg .u64 t; cvta.to.shared.u64 t, %1; cvt.u32.u64 %0, t; }" : "=r"(r) : "l"(p));
    return r;
}
__device__ __forceinline__ void cp16(unsigned d, const void* s) {
    asm volatile("cp.async.cg.shared.global [%0], [%1], 16;" :: "r"(d), "l"(s));
}
__device__ __forceinline__ void cpcommit() { asm volatile("cp.async.commit_group;" ::: "memory"); }
template <int N> __device__ __forceinline__ void cpwait() {
    asm volatile("cp.async.wait_group %0;" :: "n"(N) : "memory");
}

// pack two f32 -> bf16x2 (first arg -> low half)
__device__ __forceinline__ u32 pk_bf16(float lo, float hi) {
    u32 d; asm("cvt.rn.bf16x2.f32 %0, %1, %2;" : "=r"(d) : "f"(hi), "f"(lo)); return d;
}
__device__ __forceinline__ float bf_lo(u32 p) { return __uint_as_float(p << 16); }
__device__ __forceinline__ float bf_hi(u32 p) { return __uint_as_float(p & 0xFFFF0000u); }

__device__ __forceinline__ void split2(float x0, float x1, u32& hi, u32& lo) {
    hi = pk_bf16(x0, x1);
    lo = pk_bf16(x0 - bf_lo(hi), x1 - bf_hi(hi));
}

// D(m16n8) += A(m16k16,bf16) * B(k16n8,bf16)
__device__ __forceinline__ void mma16(float d[4], const u32 a[4], const u32 b[2]) {
    asm volatile("mma.sync.aligned.m16n8k16.row.col.f32.bf16.bf16.f32 "
        "{%0,%1,%2,%3}, {%4,%5,%6,%7}, {%8,%9}, {%0,%1,%2,%3};"
        : "+f"(d[0]), "+f"(d[1]), "+f"(d[2]), "+f"(d[3])
        : "r"(a[0]), "r"(a[1]), "r"(a[2]), "r"(a[3]), "r"(b[0]), "r"(b[1]));
}

__global__ void __launch_bounds__(THREADS, 5)
edge_embed_bf16_kernel(const float* __restrict__ edge,
                       const float* __restrict__ adj,
                       const float* __restrict__ w4,
                       const float* __restrict__ w3,
                       float* __restrict__ out)
{
    __shared__ float adj_s[NN];
    __shared__ float Sp[4][EE];
    __shared__ float Sh[EE];

    const int tid  = threadIdx.x;
    const int lane = tid & 31;
    const int warp = tid >> 5;
    const int gid  = lane >> 2;      // 0..7  (B column within group)
    const int tig  = lane & 3;       // 0..3  (k chunk / D column pair)
    const int row  = blockIdx.x;     // b*N + i

    const float* erow = edge + (size_t)row * (NN * FF);
    const float* arow = adj  + (size_t)row * NN;

    cp16(smem_u32(&adj_s[tid * 4]), arow + tid * 4);
    cpcommit();

    // ---- A = W4, 4 e-tiles pre-split in registers (k-permuted chunks) ----
    u32 Whi[4][4], Wlo[4][4];
#pragma unroll
    for (int et = 0; et < 4; ++et) {
        const int e0 = et * 16 + gid;
        float4 wa = __ldg(reinterpret_cast<const float4*>(w4 + e0 * FF) + tig);
        float4 wb = __ldg(reinterpret_cast<const float4*>(w4 + (e0 + 8) * FF) + tig);
        split2(wa.x, wa.y, Whi[et][0], Wlo[et][0]);
        split2(wb.x, wb.y, Whi[et][1], Wlo[et][1]);
        split2(wa.z, wa.w, Whi[et][2], Wlo[et][2]);
        split2(wb.z, wb.w, Whi[et][3], Wlo[et][3]);
    }

    u64 acc2[8];
#pragma unroll
    for (int i = 0; i < 8; ++i) acc2[i] = 0ULL;
    const u64 ABS2 = 0x7FFFFFFF7FFFFFFFULL;
    const u64 LRA2 = pk2(LR_A, LR_A);
    const u64 LRB2 = pk2(LR_B, LR_B);

    cpwait<0>();
    __syncthreads();

    // B = edge. Group of 8 j; lane supplies column j = jb+gid, k chunk tig.
    const float4* ev = reinterpret_cast<const float4*>(erow);
    const int jb0 = warp * 128;                    // 16 groups of 8 j per warp

    // rolling 4-deep LDG pipeline (4 LDG.128 in flight per warp)
    float4 xq[4];
#pragma unroll
    for (int p = 0; p < 4; ++p)
        xq[p] = __ldg(ev + (size_t)(jb0 + p * 8 + gid) * 4 + tig);

#pragma unroll
    for (int gg = 0; gg < 16; ++gg) {
        const int jb = jb0 + gg * 8;
        float4 c = xq[gg & 3];
        if (gg + 4 < 16)
            xq[gg & 3] = __ldg(ev + (size_t)(jb + 32 + gid) * 4 + tig);

        // B fragments (hi/lo split)
        u32 bh[2], bl[2];
        split2(c.x, c.y, bh[0], bl[0]);     // k 2t..2t+1
        split2(c.z, c.w, bh[1], bl[1]);     // k 2t+8..2t+9

        // adj pair for this thread's two D columns (j = jb+2t, jb+2t+1)
        float2 aj = *reinterpret_cast<const float2*>(&adj_s[jb + 2 * tig]);
        const u64 a01 = pk2(aj.x, aj.y);
        const u64 aA2 = fmul2(a01, LRA2);
        const u64 aB2 = fmul2(a01, LRB2);

#pragma unroll
        for (int et = 0; et < 4; ++et) {
            float d[4] = {0.f, 0.f, 0.f, 0.f};
            mma16(d, Whi[et], bh);          // hi * hi
            mma16(d, Wlo[et], bh);          // lo * hi
            mma16(d, Whi[et], bl);          // hi * lo
            u64 v01 = pk2(d[0], d[1]);
            u64 v23 = pk2(d[2], d[3]);
            acc2[et * 2]     = ffma2(aA2, v01,        acc2[et * 2]);
            acc2[et * 2]     = ffma2(aB2, v01 & ABS2, acc2[et * 2]);
            acc2[et * 2 + 1] = ffma2(aA2, v23,        acc2[et * 2 + 1]);
            acc2[et * 2 + 1] = ffma2(aB2, v23 & ABS2, acc2[et * 2 + 1]);
        }
    }

    // ---- reduce: j-parity halves, then over tig (quad) ----
    float accf[8];
#pragma unroll
    for (int i = 0; i < 8; ++i) {
        float lo, hi; upk2(acc2[i], lo, hi);
        accf[i] = lo + hi;
    }
#pragma unroll
    for (int off = 1; off <= 2; off <<= 1) {
#pragma unroll
        for (int i = 0; i < 8; ++i)
            accf[i] += __shfl_xor_sync(0xFFFFFFFFu, accf[i], off);
    }
    if (tig == 0) {
#pragma unroll
        for (int et = 0; et < 4; ++et) {
            Sp[warp][et * 16 + gid]     = accf[et * 2];
            Sp[warp][et * 16 + gid + 8] = accf[et * 2 + 1];
        }
    }
    __syncthreads();

    if (tid < EE) {
        Sh[tid] = Sp[0][tid] + Sp[1][tid] + Sp[2][tid] + Sp[3][tid];
    }
    __syncthreads();

    // ---- theta3 ----
    if (tid < EE) {
        const float4* w3v = reinterpret_cast<const float4*>(w3 + tid * EE);
        float o = 0.0f;
#pragma unroll
        for (int k = 0; k < 16; ++k) {
            float4 w = __ldg(w3v + k);
            o = fmaf(w.x, Sh[4 * k + 0], o);
            o = fmaf(w.y, Sh[4 * k + 1], o);
            o = fmaf(w.z, Sh[4 * k + 2], o);
            o = fmaf(w.w, Sh[4 * k + 3], o);
        }
        out[(size_t)row * EE + tid] = o;
    }
}

extern "C" void kernel_launch(void* const* d_in, const int* in_sizes, int n_in,
                              void* d_out, int out_size) {
    const float* edge = (const float*)d_in[0];   // (4,512,512,16) f32
    const float* adj  = (const float*)d_in[1];   // (4,512,512)    f32
    const float* w4   = (const float*)d_in[2];   // (64,16)        f32
    const float* w3   = (const float*)d_in[3];   // (64,64)        f32
    float* out = (float*)d_out;                  // (4,512,64)     f32

    edge_embed_bf16_kernel<<<BB * NN, THREADS>>>(edge, adj, w4, w3, out);
}